// round 1
// baseline (speedup 1.0000x reference)
#include <cuda_runtime.h>

// Problem constants (shapes are fixed by the dataset; N/E still read from in_sizes)
#define MAX_N 50000

// Aggregation scratch: agg[N][256] fp32 (51.2 MB). Static __device__ per the
// no-allocation rule.
__device__ float g_agg[(size_t)MAX_N * 256];

// ---------------------------------------------------------------------------
// Kernel 0: zero the aggregation buffer
// ---------------------------------------------------------------------------
__global__ void zero_agg_kernel(int n4) {
    float4* p = reinterpret_cast<float4*>(g_agg);
    int i = blockIdx.x * blockDim.x + threadIdx.x;
    int stride = gridDim.x * blockDim.x;
    float4 z = make_float4(0.f, 0.f, 0.f, 0.f);
    for (; i < n4; i += stride) p[i] = z;
}

// ---------------------------------------------------------------------------
// Kernel 1: edge messages, both directions, fused 2-layer MLP + atomic scatter
//
// Tile: 64 edges x 256 hidden per CTA, 256 threads.
// Thread tile: 8 edges x 8 hidden (warp w owns edges [8w, 8w+8), lane l owns
// hidden cols [8l, 8l+8)).  X (gathered states) staged in smem; weights
// streamed from L2 in 32-row smem tiles.
// ---------------------------------------------------------------------------
__global__ __launch_bounds__(256, 1)
void edge_kernel(const float* __restrict__ node_states,
                 const float* __restrict__ edge_feat,
                 const int*   __restrict__ from_idx,
                 const int*   __restrict__ to_idx,
                 const float* __restrict__ W1,  const float* __restrict__ b1,
                 const float* __restrict__ W2,  const float* __restrict__ b2,
                 const float* __restrict__ RW1, const float* __restrict__ Rb1,
                 const float* __restrict__ RW2, const float* __restrict__ Rb2,
                 int E)
{
    extern __shared__ float sm[];
    float* sXf = sm;              // 64*128
    float* sXt = sm + 8192;       // 64*128
    float* sEf = sm + 16384;      // 64
    float* sH  = sm + 16448;      // 64*256
    float* sW  = sm + 32832;      // 32*256
    // total 41024 floats = 164,096 B

    const int tid = threadIdx.x;
    const int e0  = blockIdx.x * 64;

    // Stage gathered node states (float4, mostly L2 hits: node_states fits L2)
    for (int t = tid; t < 64 * 32; t += 256) {
        int e = t >> 5;
        int eIdx = e0 + e;
        int ei = eIdx < E ? eIdx : 0;
        int fi = from_idx[ei];
        int ti = to_idx[ei];
        int c = t & 31;
        reinterpret_cast<float4*>(sXf)[t] =
            reinterpret_cast<const float4*>(node_states)[(size_t)fi * 32 + c];
        reinterpret_cast<float4*>(sXt)[t] =
            reinterpret_cast<const float4*>(node_states)[(size_t)ti * 32 + c];
    }
    if (tid < 64) {
        int eIdx = e0 + tid;
        sEf[tid] = (eIdx < E) ? edge_feat[eIdx] : 0.f;
    }
    __syncthreads();

    const int wg   = tid >> 5;   // warp id: edge group
    const int lane = tid & 31;   // hidden group
    const int eBase = wg * 8;
    const int j0    = lane * 8;

    for (int dir = 0; dir < 2; ++dir) {
        const float* A   = dir ? sXt : sXf;   // first half of concat
        const float* Bm  = dir ? sXf : sXt;   // second half of concat
        const float* Wa  = dir ? RW1 : W1;
        const float* ba  = dir ? Rb1 : b1;
        const float* Wb  = dir ? RW2 : W2;
        const float* bb  = dir ? Rb2 : b2;
        const int*   dst = dir ? from_idx : to_idx;

        // ---------- layer 1: h = relu(X @ W1 + b1), K = 257 ----------
        float acc[8][8];
        #pragma unroll
        for (int jj = 0; jj < 8; ++jj) {
            float bv = ba[j0 + jj];
            #pragma unroll
            for (int ii = 0; ii < 8; ++ii) acc[ii][jj] = bv;
        }

        for (int kt = 0; kt < 8; ++kt) {
            __syncthreads();
            {
                const float4* src = reinterpret_cast<const float4*>(Wa + kt * 32 * 256);
                float4* dw = reinterpret_cast<float4*>(sW);
                #pragma unroll
                for (int t0 = 0; t0 < 8; ++t0) dw[tid + t0 * 256] = src[tid + t0 * 256];
            }
            __syncthreads();
            const float* Xb = (kt < 4) ? (A + kt * 32) : (Bm + (kt - 4) * 32);
            #pragma unroll 8
            for (int kk = 0; kk < 32; ++kk) {
                float xv[8];
                #pragma unroll
                for (int ii = 0; ii < 8; ++ii) xv[ii] = Xb[(eBase + ii) * 128 + kk];
                float4 w0 = *reinterpret_cast<const float4*>(&sW[kk * 256 + j0]);
                float4 w1 = *reinterpret_cast<const float4*>(&sW[kk * 256 + j0 + 4]);
                float wv[8] = {w0.x, w0.y, w0.z, w0.w, w1.x, w1.y, w1.z, w1.w};
                #pragma unroll
                for (int ii = 0; ii < 8; ++ii)
                    #pragma unroll
                    for (int jj = 0; jj < 8; ++jj)
                        acc[ii][jj] = fmaf(xv[ii], wv[jj], acc[ii][jj]);
            }
        }
        // k = 256: edge feature column
        {
            float wv[8];
            #pragma unroll
            for (int jj = 0; jj < 8; ++jj) wv[jj] = Wa[256 * 256 + j0 + jj];
            #pragma unroll
            for (int ii = 0; ii < 8; ++ii) {
                float x = sEf[eBase + ii];
                #pragma unroll
                for (int jj = 0; jj < 8; ++jj)
                    acc[ii][jj] = fmaf(x, wv[jj], acc[ii][jj]);
            }
        }
        // ReLU -> sH
        #pragma unroll
        for (int ii = 0; ii < 8; ++ii) {
            float4 h0 = make_float4(fmaxf(acc[ii][0], 0.f), fmaxf(acc[ii][1], 0.f),
                                    fmaxf(acc[ii][2], 0.f), fmaxf(acc[ii][3], 0.f));
            float4 h1 = make_float4(fmaxf(acc[ii][4], 0.f), fmaxf(acc[ii][5], 0.f),
                                    fmaxf(acc[ii][6], 0.f), fmaxf(acc[ii][7], 0.f));
            *reinterpret_cast<float4*>(&sH[(eBase + ii) * 256 + j0])     = h0;
            *reinterpret_cast<float4*>(&sH[(eBase + ii) * 256 + j0 + 4]) = h1;
        }

        // ---------- layer 2: msg = h @ W2 + b2, K = 256 ----------
        float acc2[8][8];
        #pragma unroll
        for (int jj = 0; jj < 8; ++jj) {
            float bv = bb[j0 + jj];
            #pragma unroll
            for (int ii = 0; ii < 8; ++ii) acc2[ii][jj] = bv;
        }

        for (int kt = 0; kt < 8; ++kt) {
            __syncthreads();   // also orders sH writes above vs. reads below
            {
                const float4* src = reinterpret_cast<const float4*>(Wb + kt * 32 * 256);
                float4* dw = reinterpret_cast<float4*>(sW);
                #pragma unroll
                for (int t0 = 0; t0 < 8; ++t0) dw[tid + t0 * 256] = src[tid + t0 * 256];
            }
            __syncthreads();
            const float* Xb = sH + kt * 32;
            #pragma unroll 8
            for (int kk = 0; kk < 32; ++kk) {
                float xv[8];
                #pragma unroll
                for (int ii = 0; ii < 8; ++ii) xv[ii] = Xb[(eBase + ii) * 256 + kk];
                float4 w0 = *reinterpret_cast<const float4*>(&sW[kk * 256 + j0]);
                float4 w1 = *reinterpret_cast<const float4*>(&sW[kk * 256 + j0 + 4]);
                float wv[8] = {w0.x, w0.y, w0.z, w0.w, w1.x, w1.y, w1.z, w1.w};
                #pragma unroll
                for (int ii = 0; ii < 8; ++ii)
                    #pragma unroll
                    for (int jj = 0; jj < 8; ++jj)
                        acc2[ii][jj] = fmaf(xv[ii], wv[jj], acc2[ii][jj]);
            }
        }

        // scatter-add into agg
        #pragma unroll
        for (int ii = 0; ii < 8; ++ii) {
            int eIdx = e0 + eBase + ii;
            if (eIdx < E) {
                int d = dst[eIdx];
                float* ap = g_agg + (size_t)d * 256 + j0;
                #pragma unroll
                for (int jj = 0; jj < 8; ++jj) atomicAdd(ap + jj, acc2[ii][jj]);
            }
        }
    }
}

// ---------------------------------------------------------------------------
// Kernel 2: node update MLP + residual
// Tile: 64 nodes x (256 hidden / 128 out), 256 threads.
// ---------------------------------------------------------------------------
__global__ __launch_bounds__(256, 1)
void node_kernel(const float* __restrict__ node_states,
                 const float* __restrict__ Wn1, const float* __restrict__ bn1,
                 const float* __restrict__ Wn2, const float* __restrict__ bn2,
                 float* __restrict__ out, int N)
{
    extern __shared__ float sm[];
    float* sA = sm;            // 64*256 (agg)
    float* sS = sm + 16384;    // 64*128 (node_states)
    float* sH = sm + 24576;    // 64*256 (hidden)
    float* sW = sm + 40960;    // 32*256 (weight tile)
    // total 49152 floats = 196,608 B

    const int tid = threadIdx.x;
    const int n0  = blockIdx.x * 64;

    for (int t = tid; t < 64 * 64; t += 256) {
        int n = t >> 6, c = t & 63;
        float4 v = make_float4(0.f, 0.f, 0.f, 0.f);
        if (n0 + n < N)
            v = reinterpret_cast<const float4*>(g_agg)[(size_t)(n0 + n) * 64 + c];
        reinterpret_cast<float4*>(sA)[t] = v;
    }
    for (int t = tid; t < 64 * 32; t += 256) {
        int n = t >> 5, c = t & 31;
        float4 v = make_float4(0.f, 0.f, 0.f, 0.f);
        if (n0 + n < N)
            v = reinterpret_cast<const float4*>(node_states)[(size_t)(n0 + n) * 32 + c];
        reinterpret_cast<float4*>(sS)[t] = v;
    }
    __syncthreads();

    const int wg   = tid >> 5;
    const int lane = tid & 31;
    const int nBase = wg * 8;
    const int j0    = lane * 8;

    // ---------- layer 1: K = 384 ([agg(256) | states(128)]) ----------
    float acc[8][8];
    #pragma unroll
    for (int jj = 0; jj < 8; ++jj) {
        float bv = bn1[j0 + jj];
        #pragma unroll
        for (int ii = 0; ii < 8; ++ii) acc[ii][jj] = bv;
    }

    for (int kt = 0; kt < 12; ++kt) {
        __syncthreads();
        {
            const float4* src = reinterpret_cast<const float4*>(Wn1 + kt * 32 * 256);
            float4* dw = reinterpret_cast<float4*>(sW);
            #pragma unroll
            for (int t0 = 0; t0 < 8; ++t0) dw[tid + t0 * 256] = src[tid + t0 * 256];
        }
        __syncthreads();
        const float* Xb;
        int strd;
        if (kt < 8) { Xb = sA + kt * 32;       strd = 256; }
        else        { Xb = sS + (kt - 8) * 32; strd = 128; }
        #pragma unroll 8
        for (int kk = 0; kk < 32; ++kk) {
            float xv[8];
            #pragma unroll
            for (int ii = 0; ii < 8; ++ii) xv[ii] = Xb[(nBase + ii) * strd + kk];
            float4 w0 = *reinterpret_cast<const float4*>(&sW[kk * 256 + j0]);
            float4 w1 = *reinterpret_cast<const float4*>(&sW[kk * 256 + j0 + 4]);
            float wv[8] = {w0.x, w0.y, w0.z, w0.w, w1.x, w1.y, w1.z, w1.w};
            #pragma unroll
            for (int ii = 0; ii < 8; ++ii)
                #pragma unroll
                for (int jj = 0; jj < 8; ++jj)
                    acc[ii][jj] = fmaf(xv[ii], wv[jj], acc[ii][jj]);
        }
    }
    #pragma unroll
    for (int ii = 0; ii < 8; ++ii) {
        float4 h0 = make_float4(fmaxf(acc[ii][0], 0.f), fmaxf(acc[ii][1], 0.f),
                                fmaxf(acc[ii][2], 0.f), fmaxf(acc[ii][3], 0.f));
        float4 h1 = make_float4(fmaxf(acc[ii][4], 0.f), fmaxf(acc[ii][5], 0.f),
                                fmaxf(acc[ii][6], 0.f), fmaxf(acc[ii][7], 0.f));
        *reinterpret_cast<float4*>(&sH[(nBase + ii) * 256 + j0])     = h0;
        *reinterpret_cast<float4*>(&sH[(nBase + ii) * 256 + j0 + 4]) = h1;
    }

    // ---------- layer 2: K = 256, 128 output cols; thread tile 8x4 ----------
    const int j4 = lane * 4;
    float acc2[8][4];
    #pragma unroll
    for (int jj = 0; jj < 4; ++jj) {
        float bv = bn2[j4 + jj];
        #pragma unroll
        for (int ii = 0; ii < 8; ++ii) acc2[ii][jj] = bv;
    }

    for (int kt = 0; kt < 8; ++kt) {
        __syncthreads();   // also orders sH writes vs reads
        {
            const float4* src = reinterpret_cast<const float4*>(Wn2 + kt * 32 * 128);
            float4* dw = reinterpret_cast<float4*>(sW);
            #pragma unroll
            for (int t0 = 0; t0 < 4; ++t0) dw[tid + t0 * 256] = src[tid + t0 * 256];
        }
        __syncthreads();
        #pragma unroll 8
        for (int kk = 0; kk < 32; ++kk) {
            float xv[8];
            #pragma unroll
            for (int ii = 0; ii < 8; ++ii) xv[ii] = sH[(nBase + ii) * 256 + kt * 32 + kk];
            float4 w = *reinterpret_cast<const float4*>(&sW[kk * 128 + j4]);
            float wv[4] = {w.x, w.y, w.z, w.w};
            #pragma unroll
            for (int ii = 0; ii < 8; ++ii)
                #pragma unroll
                for (int jj = 0; jj < 4; ++jj)
                    acc2[ii][jj] = fmaf(xv[ii], wv[jj], acc2[ii][jj]);
        }
    }

    // residual + store
    #pragma unroll
    for (int ii = 0; ii < 8; ++ii) {
        int n = n0 + nBase + ii;
        if (n < N) {
            float4 s = *reinterpret_cast<const float4*>(&sS[(nBase + ii) * 128 + j4]);
            float4 o = make_float4(s.x + acc2[ii][0], s.y + acc2[ii][1],
                                   s.z + acc2[ii][2], s.w + acc2[ii][3]);
            *reinterpret_cast<float4*>(&out[(size_t)n * 128 + j4]) = o;
        }
    }
}

// ---------------------------------------------------------------------------
extern "C" void kernel_launch(void* const* d_in, const int* in_sizes, int n_in,
                              void* d_out, int out_size)
{
    const float* node_states = (const float*)d_in[0];
    const float* edge_feat   = (const float*)d_in[1];
    const int*   from_idx    = (const int*)d_in[2];
    const int*   to_idx      = (const int*)d_in[3];
    const float* W1  = (const float*)d_in[4];
    const float* b1  = (const float*)d_in[5];
    const float* W2  = (const float*)d_in[6];
    const float* b2  = (const float*)d_in[7];
    const float* RW1 = (const float*)d_in[8];
    const float* Rb1 = (const float*)d_in[9];
    const float* RW2 = (const float*)d_in[10];
    const float* Rb2 = (const float*)d_in[11];
    const float* Wn1 = (const float*)d_in[12];
    const float* bn1 = (const float*)d_in[13];
    const float* Wn2 = (const float*)d_in[14];
    const float* bn2 = (const float*)d_in[15];
    float* out = (float*)d_out;

    const int N = in_sizes[0] / 128;
    const int E = in_sizes[2];

    cudaFuncSetAttribute(edge_kernel, cudaFuncAttributeMaxDynamicSharedMemorySize, 41024 * 4);
    cudaFuncSetAttribute(node_kernel, cudaFuncAttributeMaxDynamicSharedMemorySize, 49152 * 4);

    zero_agg_kernel<<<1024, 256>>>(N * 64);
    edge_kernel<<<(E + 63) / 64, 256, 41024 * 4>>>(node_states, edge_feat, from_idx, to_idx,
                                                   W1, b1, W2, b2, RW1, Rb1, RW2, Rb2, E);
    node_kernel<<<(N + 63) / 64, 256, 49152 * 4>>>(node_states, Wn1, bn1, Wn2, bn2, out, N);
}

// round 2
// speedup vs baseline: 1.0005x; 1.0005x over previous
#include <cuda_runtime.h>

// Problem constants (shapes are fixed by the dataset; N/E still read from in_sizes)
#define MAX_N 50000

// Aggregation scratch: agg[N][256] fp32 (51.2 MB). Static __device__ per the
// no-allocation rule.
__device__ float g_agg[(size_t)MAX_N * 256];

// ---------------------------------------------------------------------------
// Kernel 0: zero the aggregation buffer
// ---------------------------------------------------------------------------
__global__ void zero_agg_kernel(int n4) {
    float4* p = reinterpret_cast<float4*>(g_agg);
    int i = blockIdx.x * blockDim.x + threadIdx.x;
    int stride = gridDim.x * blockDim.x;
    float4 z = make_float4(0.f, 0.f, 0.f, 0.f);
    for (; i < n4; i += stride) p[i] = z;
}

// ---------------------------------------------------------------------------
// Kernel 1: edge messages, both directions, fused 2-layer MLP + atomic scatter
//
// Tile: 64 edges x 256 hidden per CTA, 256 threads.
// Thread tile: 8 edges x 8 hidden (warp w owns edges [8w, 8w+8), lane l owns
// hidden cols [8l, 8l+8)).  X (gathered states) staged in smem; weights
// streamed from L2 in 32-row smem tiles.
// ---------------------------------------------------------------------------
__global__ __launch_bounds__(256, 1)
void edge_kernel(const float* __restrict__ node_states,
                 const float* __restrict__ edge_feat,
                 const int*   __restrict__ from_idx,
                 const int*   __restrict__ to_idx,
                 const float* __restrict__ W1,  const float* __restrict__ b1,
                 const float* __restrict__ W2,  const float* __restrict__ b2,
                 const float* __restrict__ RW1, const float* __restrict__ Rb1,
                 const float* __restrict__ RW2, const float* __restrict__ Rb2,
                 int E)
{
    extern __shared__ float sm[];
    float* sXf = sm;              // 64*128
    float* sXt = sm + 8192;       // 64*128
    float* sEf = sm + 16384;      // 64
    float* sH  = sm + 16448;      // 64*256
    float* sW  = sm + 32832;      // 32*256
    // total 41024 floats = 164,096 B

    const int tid = threadIdx.x;
    const int e0  = blockIdx.x * 64;

    // Stage gathered node states (float4, mostly L2 hits: node_states fits L2)
    for (int t = tid; t < 64 * 32; t += 256) {
        int e = t >> 5;
        int eIdx = e0 + e;
        int ei = eIdx < E ? eIdx : 0;
        int fi = from_idx[ei];
        int ti = to_idx[ei];
        int c = t & 31;
        reinterpret_cast<float4*>(sXf)[t] =
            reinterpret_cast<const float4*>(node_states)[(size_t)fi * 32 + c];
        reinterpret_cast<float4*>(sXt)[t] =
            reinterpret_cast<const float4*>(node_states)[(size_t)ti * 32 + c];
    }
    if (tid < 64) {
        int eIdx = e0 + tid;
        sEf[tid] = (eIdx < E) ? edge_feat[eIdx] : 0.f;
    }
    __syncthreads();

    const int wg   = tid >> 5;   // warp id: edge group
    const int lane = tid & 31;   // hidden group
    const int eBase = wg * 8;
    const int j0    = lane * 8;

    for (int dir = 0; dir < 2; ++dir) {
        const float* A   = dir ? sXt : sXf;   // first half of concat
        const float* Bm  = dir ? sXf : sXt;   // second half of concat
        const float* Wa  = dir ? RW1 : W1;
        const float* ba  = dir ? Rb1 : b1;
        const float* Wb  = dir ? RW2 : W2;
        const float* bb  = dir ? Rb2 : b2;
        const int*   dst = dir ? from_idx : to_idx;

        // ---------- layer 1: h = relu(X @ W1 + b1), K = 257 ----------
        float acc[8][8];
        #pragma unroll
        for (int jj = 0; jj < 8; ++jj) {
            float bv = ba[j0 + jj];
            #pragma unroll
            for (int ii = 0; ii < 8; ++ii) acc[ii][jj] = bv;
        }

        for (int kt = 0; kt < 8; ++kt) {
            __syncthreads();
            {
                const float4* src = reinterpret_cast<const float4*>(Wa + kt * 32 * 256);
                float4* dw = reinterpret_cast<float4*>(sW);
                #pragma unroll
                for (int t0 = 0; t0 < 8; ++t0) dw[tid + t0 * 256] = src[tid + t0 * 256];
            }
            __syncthreads();
            const float* Xb = (kt < 4) ? (A + kt * 32) : (Bm + (kt - 4) * 32);
            #pragma unroll 8
            for (int kk = 0; kk < 32; ++kk) {
                float xv[8];
                #pragma unroll
                for (int ii = 0; ii < 8; ++ii) xv[ii] = Xb[(eBase + ii) * 128 + kk];
                float4 w0 = *reinterpret_cast<const float4*>(&sW[kk * 256 + j0]);
                float4 w1 = *reinterpret_cast<const float4*>(&sW[kk * 256 + j0 + 4]);
                float wv[8] = {w0.x, w0.y, w0.z, w0.w, w1.x, w1.y, w1.z, w1.w};
                #pragma unroll
                for (int ii = 0; ii < 8; ++ii)
                    #pragma unroll
                    for (int jj = 0; jj < 8; ++jj)
                        acc[ii][jj] = fmaf(xv[ii], wv[jj], acc[ii][jj]);
            }
        }
        // k = 256: edge feature column
        {
            float wv[8];
            #pragma unroll
            for (int jj = 0; jj < 8; ++jj) wv[jj] = Wa[256 * 256 + j0 + jj];
            #pragma unroll
            for (int ii = 0; ii < 8; ++ii) {
                float x = sEf[eBase + ii];
                #pragma unroll
                for (int jj = 0; jj < 8; ++jj)
                    acc[ii][jj] = fmaf(x, wv[jj], acc[ii][jj]);
            }
        }
        // ReLU -> sH
        #pragma unroll
        for (int ii = 0; ii < 8; ++ii) {
            float4 h0 = make_float4(fmaxf(acc[ii][0], 0.f), fmaxf(acc[ii][1], 0.f),
                                    fmaxf(acc[ii][2], 0.f), fmaxf(acc[ii][3], 0.f));
            float4 h1 = make_float4(fmaxf(acc[ii][4], 0.f), fmaxf(acc[ii][5], 0.f),
                                    fmaxf(acc[ii][6], 0.f), fmaxf(acc[ii][7], 0.f));
            *reinterpret_cast<float4*>(&sH[(eBase + ii) * 256 + j0])     = h0;
            *reinterpret_cast<float4*>(&sH[(eBase + ii) * 256 + j0 + 4]) = h1;
        }

        // ---------- layer 2: msg = h @ W2 + b2, K = 256 ----------
        float acc2[8][8];
        #pragma unroll
        for (int jj = 0; jj < 8; ++jj) {
            float bv = bb[j0 + jj];
            #pragma unroll
            for (int ii = 0; ii < 8; ++ii) acc2[ii][jj] = bv;
        }

        for (int kt = 0; kt < 8; ++kt) {
            __syncthreads();   // also orders sH writes above vs. reads below
            {
                const float4* src = reinterpret_cast<const float4*>(Wb + kt * 32 * 256);
                float4* dw = reinterpret_cast<float4*>(sW);
                #pragma unroll
                for (int t0 = 0; t0 < 8; ++t0) dw[tid + t0 * 256] = src[tid + t0 * 256];
            }
            __syncthreads();
            const float* Xb = sH + kt * 32;
            #pragma unroll 8
            for (int kk = 0; kk < 32; ++kk) {
                float xv[8];
                #pragma unroll
                for (int ii = 0; ii < 8; ++ii) xv[ii] = Xb[(eBase + ii) * 256 + kk];
                float4 w0 = *reinterpret_cast<const float4*>(&sW[kk * 256 + j0]);
                float4 w1 = *reinterpret_cast<const float4*>(&sW[kk * 256 + j0 + 4]);
                float wv[8] = {w0.x, w0.y, w0.z, w0.w, w1.x, w1.y, w1.z, w1.w};
                #pragma unroll
                for (int ii = 0; ii < 8; ++ii)
                    #pragma unroll
                    for (int jj = 0; jj < 8; ++jj)
                        acc2[ii][jj] = fmaf(xv[ii], wv[jj], acc2[ii][jj]);
            }
        }

        // scatter-add into agg
        #pragma unroll
        for (int ii = 0; ii < 8; ++ii) {
            int eIdx = e0 + eBase + ii;
            if (eIdx < E) {
                int d = dst[eIdx];
                float* ap = g_agg + (size_t)d * 256 + j0;
                #pragma unroll
                for (int jj = 0; jj < 8; ++jj) atomicAdd(ap + jj, acc2[ii][jj]);
            }
        }
    }
}

// ---------------------------------------------------------------------------
// Kernel 2: node update MLP + residual
// Tile: 64 nodes x (256 hidden / 128 out), 256 threads.
// ---------------------------------------------------------------------------
__global__ __launch_bounds__(256, 1)
void node_kernel(const float* __restrict__ node_states,
                 const float* __restrict__ Wn1, const float* __restrict__ bn1,
                 const float* __restrict__ Wn2, const float* __restrict__ bn2,
                 float* __restrict__ out, int N)
{
    extern __shared__ float sm[];
    float* sA = sm;            // 64*256 (agg)
    float* sS = sm + 16384;    // 64*128 (node_states)
    float* sH = sm + 24576;    // 64*256 (hidden)
    float* sW = sm + 40960;    // 32*256 (weight tile)
    // total 49152 floats = 196,608 B

    const int tid = threadIdx.x;
    const int n0  = blockIdx.x * 64;

    for (int t = tid; t < 64 * 64; t += 256) {
        int n = t >> 6, c = t & 63;
        float4 v = make_float4(0.f, 0.f, 0.f, 0.f);
        if (n0 + n < N)
            v = reinterpret_cast<const float4*>(g_agg)[(size_t)(n0 + n) * 64 + c];
        reinterpret_cast<float4*>(sA)[t] = v;
    }
    for (int t = tid; t < 64 * 32; t += 256) {
        int n = t >> 5, c = t & 31;
        float4 v = make_float4(0.f, 0.f, 0.f, 0.f);
        if (n0 + n < N)
            v = reinterpret_cast<const float4*>(node_states)[(size_t)(n0 + n) * 32 + c];
        reinterpret_cast<float4*>(sS)[t] = v;
    }
    __syncthreads();

    const int wg   = tid >> 5;
    const int lane = tid & 31;
    const int nBase = wg * 8;
    const int j0    = lane * 8;

    // ---------- layer 1: K = 384 ([agg(256) | states(128)]) ----------
    float acc[8][8];
    #pragma unroll
    for (int jj = 0; jj < 8; ++jj) {
        float bv = bn1[j0 + jj];
        #pragma unroll
        for (int ii = 0; ii < 8; ++ii) acc[ii][jj] = bv;
    }

    for (int kt = 0; kt < 12; ++kt) {
        __syncthreads();
        {
            const float4* src = reinterpret_cast<const float4*>(Wn1 + kt * 32 * 256);
            float4* dw = reinterpret_cast<float4*>(sW);
            #pragma unroll
            for (int t0 = 0; t0 < 8; ++t0) dw[tid + t0 * 256] = src[tid + t0 * 256];
        }
        __syncthreads();
        const float* Xb;
        int strd;
        if (kt < 8) { Xb = sA + kt * 32;       strd = 256; }
        else        { Xb = sS + (kt - 8) * 32; strd = 128; }
        #pragma unroll 8
        for (int kk = 0; kk < 32; ++kk) {
            float xv[8];
            #pragma unroll
            for (int ii = 0; ii < 8; ++ii) xv[ii] = Xb[(nBase + ii) * strd + kk];
            float4 w0 = *reinterpret_cast<const float4*>(&sW[kk * 256 + j0]);
            float4 w1 = *reinterpret_cast<const float4*>(&sW[kk * 256 + j0 + 4]);
            float wv[8] = {w0.x, w0.y, w0.z, w0.w, w1.x, w1.y, w1.z, w1.w};
            #pragma unroll
            for (int ii = 0; ii < 8; ++ii)
                #pragma unroll
                for (int jj = 0; jj < 8; ++jj)
                    acc[ii][jj] = fmaf(xv[ii], wv[jj], acc[ii][jj]);
        }
    }
    #pragma unroll
    for (int ii = 0; ii < 8; ++ii) {
        float4 h0 = make_float4(fmaxf(acc[ii][0], 0.f), fmaxf(acc[ii][1], 0.f),
                                fmaxf(acc[ii][2], 0.f), fmaxf(acc[ii][3], 0.f));
        float4 h1 = make_float4(fmaxf(acc[ii][4], 0.f), fmaxf(acc[ii][5], 0.f),
                                fmaxf(acc[ii][6], 0.f), fmaxf(acc[ii][7], 0.f));
        *reinterpret_cast<float4*>(&sH[(nBase + ii) * 256 + j0])     = h0;
        *reinterpret_cast<float4*>(&sH[(nBase + ii) * 256 + j0 + 4]) = h1;
    }

    // ---------- layer 2: K = 256, 128 output cols; thread tile 8x4 ----------
    const int j4 = lane * 4;
    float acc2[8][4];
    #pragma unroll
    for (int jj = 0; jj < 4; ++jj) {
        float bv = bn2[j4 + jj];
        #pragma unroll
        for (int ii = 0; ii < 8; ++ii) acc2[ii][jj] = bv;
    }

    for (int kt = 0; kt < 8; ++kt) {
        __syncthreads();   // also orders sH writes vs reads
        {
            const float4* src = reinterpret_cast<const float4*>(Wn2 + kt * 32 * 128);
            float4* dw = reinterpret_cast<float4*>(sW);
            #pragma unroll
            for (int t0 = 0; t0 < 4; ++t0) dw[tid + t0 * 256] = src[tid + t0 * 256];
        }
        __syncthreads();
        #pragma unroll 8
        for (int kk = 0; kk < 32; ++kk) {
            float xv[8];
            #pragma unroll
            for (int ii = 0; ii < 8; ++ii) xv[ii] = sH[(nBase + ii) * 256 + kt * 32 + kk];
            float4 w = *reinterpret_cast<const float4*>(&sW[kk * 128 + j4]);
            float wv[4] = {w.x, w.y, w.z, w.w};
            #pragma unroll
            for (int ii = 0; ii < 8; ++ii)
                #pragma unroll
                for (int jj = 0; jj < 4; ++jj)
                    acc2[ii][jj] = fmaf(xv[ii], wv[jj], acc2[ii][jj]);
        }
    }

    // residual + store
    #pragma unroll
    for (int ii = 0; ii < 8; ++ii) {
        int n = n0 + nBase + ii;
        if (n < N) {
            float4 s = *reinterpret_cast<const float4*>(&sS[(nBase + ii) * 128 + j4]);
            float4 o = make_float4(s.x + acc2[ii][0], s.y + acc2[ii][1],
                                   s.z + acc2[ii][2], s.w + acc2[ii][3]);
            *reinterpret_cast<float4*>(&out[(size_t)n * 128 + j4]) = o;
        }
    }
}

// ---------------------------------------------------------------------------
extern "C" void kernel_launch(void* const* d_in, const int* in_sizes, int n_in,
                              void* d_out, int out_size)
{
    const float* node_states = (const float*)d_in[0];
    const float* edge_feat   = (const float*)d_in[1];
    const int*   from_idx    = (const int*)d_in[2];
    const int*   to_idx      = (const int*)d_in[3];
    const float* W1  = (const float*)d_in[4];
    const float* b1  = (const float*)d_in[5];
    const float* W2  = (const float*)d_in[6];
    const float* b2  = (const float*)d_in[7];
    const float* RW1 = (const float*)d_in[8];
    const float* Rb1 = (const float*)d_in[9];
    const float* RW2 = (const float*)d_in[10];
    const float* Rb2 = (const float*)d_in[11];
    const float* Wn1 = (const float*)d_in[12];
    const float* bn1 = (const float*)d_in[13];
    const float* Wn2 = (const float*)d_in[14];
    const float* bn2 = (const float*)d_in[15];
    float* out = (float*)d_out;

    const int N = in_sizes[0] / 128;
    const int E = in_sizes[2];

    cudaFuncSetAttribute(edge_kernel, cudaFuncAttributeMaxDynamicSharedMemorySize, 41024 * 4);
    cudaFuncSetAttribute(node_kernel, cudaFuncAttributeMaxDynamicSharedMemorySize, 49152 * 4);

    zero_agg_kernel<<<1024, 256>>>(N * 64);
    edge_kernel<<<(E + 63) / 64, 256, 41024 * 4>>>(node_states, edge_feat, from_idx, to_idx,
                                                   W1, b1, W2, b2, RW1, Rb1, RW2, Rb2, E);
    node_kernel<<<(N + 63) / 64, 256, 49152 * 4>>>(node_states, Wn1, bn1, Wn2, bn2, out, N);
}

// round 4
// speedup vs baseline: 2.2301x; 2.2290x over previous
#include <cuda_runtime.h>
#include <cuda_fp16.h>
#include <cstdint>

#define MAX_N 50000

// ---------------- device scratch (no allocation allowed) -------------------
__device__ float  g_agg[(size_t)MAX_N * 256];       // [N][256] aggregation
__device__ __half g_w1[2][2][65536];                // [dir][hi/lo][n*256+k] fp16
__device__ __half g_w2[2][2][65536];

// ---------------- small asm helpers ----------------------------------------
__device__ __forceinline__ uint32_t smem_u32(const void* p) {
    uint32_t a;
    asm("{ .reg .u64 t; cvta.to.shared.u64 t, %1; cvt.u32.u64 %0, t; }" : "=r"(a) : "l"(p));
    return a;
}
__device__ __forceinline__ void cpa16(uint32_t dst, const void* src) {
    asm volatile("cp.async.cg.shared.global [%0], [%1], 16;" :: "r"(dst), "l"(src));
}
#define CP_COMMIT() asm volatile("cp.async.commit_group;" ::: "memory")
#define CP_WAIT(n)  asm volatile("cp.async.wait_group %0;" :: "n"(n) : "memory")

__device__ __forceinline__ void ldsm4(uint32_t* r, uint32_t addr) {
    asm volatile("ldmatrix.sync.aligned.m8n8.x4.shared.b16 {%0,%1,%2,%3}, [%4];"
                 : "=r"(r[0]), "=r"(r[1]), "=r"(r[2]), "=r"(r[3]) : "r"(addr));
}
__device__ __forceinline__ void ldsm2(uint32_t* r, uint32_t addr) {
    asm volatile("ldmatrix.sync.aligned.m8n8.x2.shared.b16 {%0,%1}, [%2];"
                 : "=r"(r[0]), "=r"(r[1]) : "r"(addr));
}
__device__ __forceinline__ void mma16816(float* c, const uint32_t* a, const uint32_t* b) {
    asm volatile("mma.sync.aligned.m16n8k16.row.col.f32.f16.f16.f32 "
                 "{%0,%1,%2,%3}, {%4,%5,%6,%7}, {%8,%9}, {%0,%1,%2,%3};"
                 : "+f"(c[0]), "+f"(c[1]), "+f"(c[2]), "+f"(c[3])
                 : "r"(a[0]), "r"(a[1]), "r"(a[2]), "r"(a[3]), "r"(b[0]), "r"(b[1]));
}
__device__ __forceinline__ void red2(float* p, float x, float y) {
    asm volatile("red.global.add.v2.f32 [%0], {%1,%2};" :: "l"(p), "f"(x), "f"(y) : "memory");
}
__device__ __forceinline__ uint32_t pack_hi(float x, float y, uint32_t& lo) {
    __half hx = __float2half_rn(x), hy = __float2half_rn(y);
    __half lx = __float2half_rn(x - __half2float(hx));
    __half ly = __float2half_rn(y - __half2float(hy));
    __half2 l2 = __halves2half2(lx, ly);
    lo = *reinterpret_cast<uint32_t*>(&l2);
    __half2 h2 = __halves2half2(hx, hy);
    return *reinterpret_cast<uint32_t*>(&h2);
}

// ---------------- smem layout (byte offsets) -------------------------------
// X buffers: [64][136] halfs each (17,408B)
#define XF_HI 0
#define XF_LO 17408
#define XT_HI 34816
#define XT_LO 52224
// H buffers: [64][264] halfs (33,792B each)
#define SH_HI 69632
#define SH_LO 103424
// W stages: [2 stages][hi/lo] of [256][40] halfs (20,480B each)
#define SW_BASE 137216
// fp32 regions
#define SBIAS 219136
#define SWEF  220160
#define SEF   221184
#define EDGE_SMEM 221440

// ---------------- prep: transpose + fp16 hi/lo split -----------------------
__global__ void prep_w_kernel(const float* __restrict__ W, __half* __restrict__ oh,
                              __half* __restrict__ ol) {
    int i = blockIdx.x * 256 + threadIdx.x;      // i = n*256 + k
    if (i >= 65536) return;
    int n = i >> 8, k = i & 255;
    float v = W[k * 256 + n];
    __half h = __float2half_rn(v);
    oh[i] = h;
    ol[i] = __float2half_rn(v - __half2float(h));
}

__global__ void zero_agg_kernel(int n4) {
    float4* p = reinterpret_cast<float4*>(g_agg);
    int i = blockIdx.x * blockDim.x + threadIdx.x;
    int stride = gridDim.x * blockDim.x;
    float4 z = make_float4(0.f, 0.f, 0.f, 0.f);
    for (; i < n4; i += stride) p[i] = z;
}

// ---------------- K=256 GEMM phase: cp.async double-buffered ---------------
// A: fp16 hi/lo fragments from smem (addrs precomputed per lane), K split in
// two 128-halves (aH0/aH1). B: weights [n][k] hi/lo streamed in 32-K chunks.
__device__ __forceinline__ void gemm_phase(
    const __half* __restrict__ gh, const __half* __restrict__ gl,
    uint32_t smb, int tid,
    uint32_t aH0, uint32_t aL0, uint32_t aH1, uint32_t aL1,
    uint32_t bB, float acc[16][4])
{
    auto copy_chunk = [&](int s, int c) {
        #pragma unroll
        for (int i = 0; i < 8; ++i) {
            int idx = i * 256 + tid;
            int h = idx >> 10, r = idx & 1023;
            int n = r >> 2, seg = r & 3;
            const __half* src = (h ? gl : gh) + n * 256 + c * 32 + seg * 8;
            uint32_t dst = smb + SW_BASE + (uint32_t)(s * 40960 + h * 20480 + n * 80 + seg * 16);
            cpa16(dst, src);
        }
    };

    copy_chunk(0, 0);
    CP_COMMIT();
    for (int c = 0; c < 8; ++c) {
        const int s = c & 1;
        if (c < 7) { copy_chunk(s ^ 1, c + 1); CP_COMMIT(); CP_WAIT(1); }
        else       { CP_WAIT(0); }
        __syncthreads();
        #pragma unroll
        for (int ks = 0; ks < 2; ++ks) {
            const int step = c * 2 + ks;
            uint32_t ah = ((step < 8) ? aH0 : aH1) + (step & 7) * 32;
            uint32_t al = ((step < 8) ? aL0 : aL1) + (step & 7) * 32;
            uint32_t Ah[4], Al[4];
            ldsm4(Ah, ah);
            ldsm4(Al, al);
            const uint32_t wrow = smb + SW_BASE + (uint32_t)(s * 40960) + bB + ks * 32;
            #pragma unroll
            for (int nf = 0; nf < 16; ++nf) {
                uint32_t Bh[2], Bl[2];
                ldsm2(Bh, wrow + nf * 640);
                ldsm2(Bl, wrow + nf * 640 + 20480);
                mma16816(acc[nf], Ah, Bh);
                mma16816(acc[nf], Ah, Bl);
                mma16816(acc[nf], Al, Bh);
            }
        }
        __syncthreads();
    }
}

// ---------------- edge kernel: both directions, HMMA fp16-split ------------
__global__ __launch_bounds__(256, 1)
void edge_mma_kernel(const float* __restrict__ ns, const float* __restrict__ ef,
                     const int* __restrict__ fidx, const int* __restrict__ tidx,
                     const float* __restrict__ W1, const float* __restrict__ RW1,
                     const float* __restrict__ b1, const float* __restrict__ b2,
                     const float* __restrict__ Rb1, const float* __restrict__ Rb2,
                     int E)
{
    extern __shared__ float smf[];
    char* smc = reinterpret_cast<char*>(smf);
    const uint32_t smb = smem_u32(smf);
    const int tid = threadIdx.x;
    const int wid = tid >> 5, lane = tid & 31;
    const int wm = wid & 3, wn = wid >> 2;
    const int m0 = wm * 16, n0 = wn * 128;
    const int e0 = blockIdx.x * 64;

    float* sBiasF = reinterpret_cast<float*>(smc + SBIAS);
    float* sWefF  = reinterpret_cast<float*>(smc + SWEF);
    float* sEfF   = reinterpret_cast<float*>(smc + SEF);

    // ---- gather X (once, shared by both directions), split to fp16 hi/lo ---
    {
        const int row = tid >> 2, q = tid & 3;
        int e = e0 + row; if (e >= E) e = E - 1;
        const float4* pf = reinterpret_cast<const float4*>(ns + (size_t)fidx[e] * 128 + q * 32);
        const float4* pt = reinterpret_cast<const float4*>(ns + (size_t)tidx[e] * 128 + q * 32);
        const uint32_t dst = (uint32_t)(row * 136 + q * 32) * 2;
        #pragma unroll
        for (int j = 0; j < 8; ++j) {
            float4 v = pf[j];
            uint32_t lo0, lo1;
            uint32_t hi0 = pack_hi(v.x, v.y, lo0);
            uint32_t hi1 = pack_hi(v.z, v.w, lo1);
            *reinterpret_cast<uint32_t*>(smc + XF_HI + dst + j * 8)     = hi0;
            *reinterpret_cast<uint32_t*>(smc + XF_HI + dst + j * 8 + 4) = hi1;
            *reinterpret_cast<uint32_t*>(smc + XF_LO + dst + j * 8)     = lo0;
            *reinterpret_cast<uint32_t*>(smc + XF_LO + dst + j * 8 + 4) = lo1;
            v = pt[j];
            hi0 = pack_hi(v.x, v.y, lo0);
            hi1 = pack_hi(v.z, v.w, lo1);
            *reinterpret_cast<uint32_t*>(smc + XT_HI + dst + j * 8)     = hi0;
            *reinterpret_cast<uint32_t*>(smc + XT_HI + dst + j * 8 + 4) = hi1;
            *reinterpret_cast<uint32_t*>(smc + XT_LO + dst + j * 8)     = lo0;
            *reinterpret_cast<uint32_t*>(smc + XT_LO + dst + j * 8 + 4) = lo1;
        }
        if (tid < 64) sEfF[tid] = (e0 + tid < E) ? ef[e0 + tid] : 0.f;
    }

    // lane-resolved fragment address components
    const int rA = (lane & 7) + ((lane >> 3) & 1) * 8;   // row within 16
    const int cAo = (lane >> 4) * 8;                     // col offset 0/8
    const uint32_t bB = (uint32_t)(((n0 + (lane & 7)) * 40 + ((lane >> 3) & 1) * 8) * 2);

    float acc[16][4];

    for (int dir = 0; dir < 2; ++dir) {
        const int* iD = dir ? fidx : tidx;
        const float* bias1 = dir ? Rb1 : b1;
        const float* bias2 = dir ? Rb2 : b2;
        const float* wef = (dir ? RW1 : W1) + 65536;   // row k=256 of W1
        const __half* g1h = g_w1[dir][0]; const __half* g1l = g_w1[dir][1];
        const __half* g2h = g_w2[dir][0]; const __half* g2l = g_w2[dir][1];
        const uint32_t fHI = dir ? XT_HI : XF_HI, fLO = dir ? XT_LO : XF_LO;
        const uint32_t sHI = dir ? XF_HI : XT_HI, sLO = dir ? XF_LO : XT_LO;

        __syncthreads();
        sBiasF[tid] = bias1[tid];
        sWefF[tid]  = wef[tid];
        __syncthreads();

        // ----------------- layer 1: K=256 MMA + fp32 ef rank-1 --------------
        #pragma unroll
        for (int nf = 0; nf < 16; ++nf) {
            int cc = n0 + nf * 8 + (lane & 3) * 2;
            acc[nf][0] = sBiasF[cc];
            acc[nf][1] = sBiasF[cc + 1];
            acc[nf][2] = acc[nf][0];
            acc[nf][3] = acc[nf][1];
        }
        {
            uint32_t off = (uint32_t)(((m0 + rA) * 136 + cAo) * 2);
            gemm_phase(g1h, g1l, smb, tid,
                       smb + fHI + off, smb + fLO + off,
                       smb + sHI + off, smb + sLO + off, bB, acc);
        }
        // epilogue: ef column (exact fp32), bias already in, ReLU, split -> sH
        {
            const float efr  = sEfF[m0 + (lane >> 2)];
            const float efr8 = sEfF[m0 + 8 + (lane >> 2)];
            const int r0 = m0 + (lane >> 2);
            #pragma unroll
            for (int nf = 0; nf < 16; ++nf) {
                int cc = n0 + nf * 8 + (lane & 3) * 2;
                float w0 = sWefF[cc], w1 = sWefF[cc + 1];
                float x0 = fmaxf(acc[nf][0] + efr * w0, 0.f);
                float x1 = fmaxf(acc[nf][1] + efr * w1, 0.f);
                float x2 = fmaxf(acc[nf][2] + efr8 * w0, 0.f);
                float x3 = fmaxf(acc[nf][3] + efr8 * w1, 0.f);
                uint32_t lo0, lo1;
                uint32_t hi0 = pack_hi(x0, x1, lo0);
                uint32_t hi1 = pack_hi(x2, x3, lo1);
                uint32_t d0 = (uint32_t)((r0 * 264 + cc) * 2);
                uint32_t d1 = (uint32_t)(((r0 + 8) * 264 + cc) * 2);
                *reinterpret_cast<uint32_t*>(smc + SH_HI + d0) = hi0;
                *reinterpret_cast<uint32_t*>(smc + SH_LO + d0) = lo0;
                *reinterpret_cast<uint32_t*>(smc + SH_HI + d1) = hi1;
                *reinterpret_cast<uint32_t*>(smc + SH_LO + d1) = lo1;
            }
        }
        __syncthreads();
        sBiasF[tid] = bias2[tid];
        __syncthreads();

        // ----------------- layer 2: K=256 over H -----------------------------
        #pragma unroll
        for (int nf = 0; nf < 16; ++nf) {
            int cc = n0 + nf * 8 + (lane & 3) * 2;
            acc[nf][0] = sBiasF[cc];
            acc[nf][1] = sBiasF[cc + 1];
            acc[nf][2] = acc[nf][0];
            acc[nf][3] = acc[nf][1];
        }
        {
            uint32_t off = (uint32_t)(((m0 + rA) * 264 + cAo) * 2);
            uint32_t h0 = smb + SH_HI + off, l0 = smb + SH_LO + off;
            gemm_phase(g2h, g2l, smb, tid, h0, l0, h0 + 256, l0 + 256, bB, acc);
        }

        // ----------------- scatter: red.v2 into g_agg ------------------------
        {
            const int er = e0 + m0 + (lane >> 2);
            const int er8 = er + 8;
            const int d0 = (er < E) ? iD[er] : 0;
            const int d8 = (er8 < E) ? iD[er8] : 0;
            float* p0 = g_agg + (size_t)d0 * 256;
            float* p8 = g_agg + (size_t)d8 * 256;
            #pragma unroll
            for (int nf = 0; nf < 16; ++nf) {
                int cc = n0 + nf * 8 + (lane & 3) * 2;
                if (er < E)  red2(p0 + cc, acc[nf][0], acc[nf][1]);
                if (er8 < E) red2(p8 + cc, acc[nf][2], acc[nf][3]);
            }
        }
    }
}

// ---------------- node update MLP + residual (FFMA, proven) ----------------
__global__ __launch_bounds__(256, 1)
void node_kernel(const float* __restrict__ node_states,
                 const float* __restrict__ Wn1, const float* __restrict__ bn1,
                 const float* __restrict__ Wn2, const float* __restrict__ bn2,
                 float* __restrict__ out, int N)
{
    extern __shared__ float sm[];
    float* sA = sm;            // 64*256
    float* sS = sm + 16384;    // 64*128
    float* sH = sm + 24576;    // 64*256
    float* sW = sm + 40960;    // 32*256

    const int tid = threadIdx.x;
    const int n0  = blockIdx.x * 64;

    for (int t = tid; t < 64 * 64; t += 256) {
        int n = t >> 6, c = t & 63;
        float4 v = make_float4(0.f, 0.f, 0.f, 0.f);
        if (n0 + n < N)
            v = reinterpret_cast<const float4*>(g_agg)[(size_t)(n0 + n) * 64 + c];
        reinterpret_cast<float4*>(sA)[t] = v;
    }
    for (int t = tid; t < 64 * 32; t += 256) {
        int n = t >> 5, c = t & 31;
        float4 v = make_float4(0.f, 0.f, 0.f, 0.f);
        if (n0 + n < N)
            v = reinterpret_cast<const float4*>(node_states)[(size_t)(n0 + n) * 32 + c];
        reinterpret_cast<float4*>(sS)[t] = v;
    }
    __syncthreads();

    const int wg = tid >> 5, lane = tid & 31;
    const int nBase = wg * 8, j0 = lane * 8;

    float acc[8][8];
    #pragma unroll
    for (int jj = 0; jj < 8; ++jj) {
        float bv = bn1[j0 + jj];
        #pragma unroll
        for (int ii = 0; ii < 8; ++ii) acc[ii][jj] = bv;
    }
    for (int kt = 0; kt < 12; ++kt) {
        __syncthreads();
        {
            const float4* src = reinterpret_cast<const float4*>(Wn1 + kt * 32 * 256);
            float4* dw = reinterpret_cast<float4*>(sW);
            #pragma unroll
            for (int t0 = 0; t0 < 8; ++t0) dw[tid + t0 * 256] = src[tid + t0 * 256];
        }
        __syncthreads();
        const float* Xb; int strd;
        if (kt < 8) { Xb = sA + kt * 32;       strd = 256; }
        else        { Xb = sS + (kt - 8) * 32; strd = 128; }
        #pragma unroll 8
        for (int kk = 0; kk < 32; ++kk) {
            float xv[8];
            #pragma unroll
            for (int ii = 0; ii < 8; ++ii) xv[ii] = Xb[(nBase + ii) * strd + kk];
            float4 w0 = *reinterpret_cast<const float4*>(&sW[kk * 256 + j0]);
            float4 w1 = *reinterpret_cast<const float4*>(&sW[kk * 256 + j0 + 4]);
            float wv[8] = {w0.x, w0.y, w0.z, w0.w, w1.x, w1.y, w1.z, w1.w};
            #pragma unroll
            for (int ii = 0; ii < 8; ++ii)
                #pragma unroll
                for (int jj = 0; jj < 8; ++jj)
                    acc[ii][jj] = fmaf(xv[ii], wv[jj], acc[ii][jj]);
        }
    }
    #pragma unroll
    for (int ii = 0; ii < 8; ++ii) {
        float4 h0 = make_float4(fmaxf(acc[ii][0], 0.f), fmaxf(acc[ii][1], 0.f),
                                fmaxf(acc[ii][2], 0.f), fmaxf(acc[ii][3], 0.f));
        float4 h1 = make_float4(fmaxf(acc[ii][4], 0.f), fmaxf(acc[ii][5], 0.f),
                                fmaxf(acc[ii][6], 0.f), fmaxf(acc[ii][7], 0.f));
        *reinterpret_cast<float4*>(&sH[(nBase + ii) * 256 + j0])     = h0;
        *reinterpret_cast<float4*>(&sH[(nBase + ii) * 256 + j0 + 4]) = h1;
    }

    const int j4 = lane * 4;
    float acc2[8][4];
    #pragma unroll
    for (int jj = 0; jj < 4; ++jj) {
        float bv = bn2[j4 + jj];
        #pragma unroll
        for (int ii = 0; ii < 8; ++ii) acc2[ii][jj] = bv;
    }
    for (int kt = 0; kt < 8; ++kt) {
        __syncthreads();
        {
            const float4* src = reinterpret_cast<const float4*>(Wn2 + kt * 32 * 128);
            float4* dw = reinterpret_cast<float4*>(sW);
            #pragma unroll
            for (int t0 = 0; t0 < 4; ++t0) dw[tid + t0 * 256] = src[tid + t0 * 256];
        }
        __syncthreads();
        #pragma unroll 8
        for (int kk = 0; kk < 32; ++kk) {
            float xv[8];
            #pragma unroll
            for (int ii = 0; ii < 8; ++ii) xv[ii] = sH[(nBase + ii) * 256 + kt * 32 + kk];
            float4 w = *reinterpret_cast<const float4*>(&sW[kk * 128 + j4]);
            float wv[4] = {w.x, w.y, w.z, w.w};
            #pragma unroll
            for (int ii = 0; ii < 8; ++ii)
                #pragma unroll
                for (int jj = 0; jj < 4; ++jj)
                    acc2[ii][jj] = fmaf(xv[ii], wv[jj], acc2[ii][jj]);
        }
    }
    #pragma unroll
    for (int ii = 0; ii < 8; ++ii) {
        int n = n0 + nBase + ii;
        if (n < N) {
            float4 s = *reinterpret_cast<const float4*>(&sS[(nBase + ii) * 128 + j4]);
            float4 o = make_float4(s.x + acc2[ii][0], s.y + acc2[ii][1],
                                   s.z + acc2[ii][2], s.w + acc2[ii][3]);
            *reinterpret_cast<float4*>(&out[(size_t)n * 128 + j4]) = o;
        }
    }
}

// ---------------------------------------------------------------------------
extern "C" void kernel_launch(void* const* d_in, const int* in_sizes, int n_in,
                              void* d_out, int out_size)
{
    const float* node_states = (const float*)d_in[0];
    const float* edge_feat   = (const float*)d_in[1];
    const int*   from_idx    = (const int*)d_in[2];
    const int*   to_idx      = (const int*)d_in[3];
    const float* W1  = (const float*)d_in[4];
    const float* b1  = (const float*)d_in[5];
    const float* W2  = (const float*)d_in[6];
    const float* b2  = (const float*)d_in[7];
    const float* RW1 = (const float*)d_in[8];
    const float* Rb1 = (const float*)d_in[9];
    const float* RW2 = (const float*)d_in[10];
    const float* Rb2 = (const float*)d_in[11];
    const float* Wn1 = (const float*)d_in[12];
    const float* bn1 = (const float*)d_in[13];
    const float* Wn2 = (const float*)d_in[14];
    const float* bn2 = (const float*)d_in[15];
    float* out = (float*)d_out;

    const int N = in_sizes[0] / 128;
    const int E = in_sizes[2];

    __half* w1p; __half* w2p;
    cudaGetSymbolAddress((void**)&w1p, g_w1);
    cudaGetSymbolAddress((void**)&w2p, g_w2);

    cudaFuncSetAttribute(edge_mma_kernel, cudaFuncAttributeMaxDynamicSharedMemorySize, EDGE_SMEM);
    cudaFuncSetAttribute(node_kernel, cudaFuncAttributeMaxDynamicSharedMemorySize, 49152 * 4);

    zero_agg_kernel<<<1024, 256>>>(N * 64);
    prep_w_kernel<<<256, 256>>>(W1,  w1p,              w1p + 65536);
    prep_w_kernel<<<256, 256>>>(RW1, w1p + 2 * 65536,  w1p + 3 * 65536);
    prep_w_kernel<<<256, 256>>>(W2,  w2p,              w2p + 65536);
    prep_w_kernel<<<256, 256>>>(RW2, w2p + 2 * 65536,  w2p + 3 * 65536);
    edge_mma_kernel<<<(E + 63) / 64, 256, EDGE_SMEM>>>(
        node_states, edge_feat, from_idx, to_idx, W1, RW1, b1, b2, Rb1, Rb2, E);
    node_kernel<<<(N + 63) / 64, 256, 49152 * 4>>>(node_states, Wn1, bn1, Wn2, bn2, out, N);
}

// round 5
// speedup vs baseline: 2.2400x; 1.0044x over previous
#include <cuda_runtime.h>
#include <cuda_fp16.h>
#include <cstdint>

#define MAX_N 50000

// ---------------- device scratch (no allocation allowed) -------------------
__device__ float  g_agg[(size_t)MAX_N * 256];       // [N][256] aggregation
__device__ __half g_w1[2][2][65536];                // [dir][hi/lo][n*256+k] fp16
__device__ __half g_w2[2][2][65536];

// ---------------- small asm helpers ----------------------------------------
__device__ __forceinline__ uint32_t smem_u32(const void* p) {
    uint32_t a;
    asm("{ .reg .u64 t; cvta.to.shared.u64 t, %1; cvt.u32.u64 %0, t; }" : "=r"(a) : "l"(p));
    return a;
}
__device__ __forceinline__ void cpa16(uint32_t dst, const void* src) {
    asm volatile("cp.async.cg.shared.global [%0], [%1], 16;" :: "r"(dst), "l"(src));
}
#define CP_COMMIT() asm volatile("cp.async.commit_group;" ::: "memory")
#define CP_WAIT(n)  asm volatile("cp.async.wait_group %0;" :: "n"(n) : "memory")

__device__ __forceinline__ void ldsm4(uint32_t* r, uint32_t addr) {
    asm volatile("ldmatrix.sync.aligned.m8n8.x4.shared.b16 {%0,%1,%2,%3}, [%4];"
                 : "=r"(r[0]), "=r"(r[1]), "=r"(r[2]), "=r"(r[3]) : "r"(addr));
}
__device__ __forceinline__ void ldsm2(uint32_t* r, uint32_t addr) {
    asm volatile("ldmatrix.sync.aligned.m8n8.x2.shared.b16 {%0,%1}, [%2];"
                 : "=r"(r[0]), "=r"(r[1]) : "r"(addr));
}
__device__ __forceinline__ void mma16816(float* c, const uint32_t* a, const uint32_t* b) {
    asm volatile("mma.sync.aligned.m16n8k16.row.col.f32.f16.f16.f32 "
                 "{%0,%1,%2,%3}, {%4,%5,%6,%7}, {%8,%9}, {%0,%1,%2,%3};"
                 : "+f"(c[0]), "+f"(c[1]), "+f"(c[2]), "+f"(c[3])
                 : "r"(a[0]), "r"(a[1]), "r"(a[2]), "r"(a[3]), "r"(b[0]), "r"(b[1]));
}
__device__ __forceinline__ void red2(float* p, float x, float y) {
    asm volatile("red.global.add.v2.f32 [%0], {%1,%2};" :: "l"(p), "f"(x), "f"(y) : "memory");
}
__device__ __forceinline__ uint32_t pack_hi(float x, float y, uint32_t& lo) {
    __half hx = __float2half_rn(x), hy = __float2half_rn(y);
    __half lx = __float2half_rn(x - __half2float(hx));
    __half ly = __float2half_rn(y - __half2float(hy));
    __half2 l2 = __halves2half2(lx, ly);
    lo = *reinterpret_cast<uint32_t*>(&l2);
    __half2 h2 = __halves2half2(hx, hy);
    return *reinterpret_cast<uint32_t*>(&h2);
}

// ---------------- smem layout (byte offsets) -------------------------------
// X buffers: [64][136] halfs each (17,408B)
#define XF_HI 0
#define XF_LO 17408
#define XT_HI 34816
#define XT_LO 52224
// H buffers: [64][264] halfs (33,792B each)
#define SH_HI 69632
#define SH_LO 103424
// W stages: [2 stages][hi/lo] of [256][40] halfs (20,480B each)
#define SW_BASE 137216
// fp32 regions
#define SBIAS 219136
#define SWEF  220160
#define SEF   221184
#define EDGE_SMEM 221440

// ---------------- prep: transpose + fp16 hi/lo split -----------------------
__global__ void prep_w_kernel(const float* __restrict__ W, __half* __restrict__ oh,
                              __half* __restrict__ ol) {
    int i = blockIdx.x * 256 + threadIdx.x;      // i = n*256 + k
    if (i >= 65536) return;
    int n = i >> 8, k = i & 255;
    float v = W[k * 256 + n];
    __half h = __float2half_rn(v);
    oh[i] = h;
    ol[i] = __float2half_rn(v - __half2float(h));
}

__global__ void zero_agg_kernel(int n4) {
    float4* p = reinterpret_cast<float4*>(g_agg);
    int i = blockIdx.x * blockDim.x + threadIdx.x;
    int stride = gridDim.x * blockDim.x;
    float4 z = make_float4(0.f, 0.f, 0.f, 0.f);
    for (; i < n4; i += stride) p[i] = z;
}

// ---------------- K=256 GEMM phase: cp.async double-buffered ---------------
// 16 warps: 4 m-tiles x 4 n-tiles; warp tile 16x64 (8 n-fragments).
// A: fp16 hi/lo fragments from smem; B: weights [n][k] hi/lo streamed in
// 32-K chunks.
__device__ __forceinline__ void gemm_phase(
    const __half* __restrict__ gh, const __half* __restrict__ gl,
    uint32_t smb, int tid,
    uint32_t aH0, uint32_t aL0, uint32_t aH1, uint32_t aL1,
    uint32_t bB, float acc[8][4])
{
    auto copy_chunk = [&](int s, int c) {
        #pragma unroll
        for (int i = 0; i < 4; ++i) {
            int idx = i * 512 + tid;
            int h = idx >> 10, r = idx & 1023;
            int n = r >> 2, seg = r & 3;
            const __half* src = (h ? gl : gh) + n * 256 + c * 32 + seg * 8;
            uint32_t dst = smb + SW_BASE + (uint32_t)(s * 40960 + h * 20480 + n * 80 + seg * 16);
            cpa16(dst, src);
        }
    };

    copy_chunk(0, 0);
    CP_COMMIT();
    for (int c = 0; c < 8; ++c) {
        const int s = c & 1;
        if (c < 7) { copy_chunk(s ^ 1, c + 1); CP_COMMIT(); CP_WAIT(1); }
        else       { CP_WAIT(0); }
        __syncthreads();
        #pragma unroll
        for (int ks = 0; ks < 2; ++ks) {
            const int step = c * 2 + ks;
            uint32_t ah = ((step < 8) ? aH0 : aH1) + (step & 7) * 32;
            uint32_t al = ((step < 8) ? aL0 : aL1) + (step & 7) * 32;
            uint32_t Ah[4], Al[4];
            ldsm4(Ah, ah);
            ldsm4(Al, al);
            const uint32_t wrow = smb + SW_BASE + (uint32_t)(s * 40960) + bB + ks * 32;
            #pragma unroll
            for (int nf = 0; nf < 8; ++nf) {
                uint32_t Bh[2], Bl[2];
                ldsm2(Bh, wrow + nf * 640);
                ldsm2(Bl, wrow + nf * 640 + 20480);
                mma16816(acc[nf], Ah, Bh);
                mma16816(acc[nf], Ah, Bl);
                mma16816(acc[nf], Al, Bh);
            }
        }
        __syncthreads();
    }
}

// ---------------- edge kernel: both directions, HMMA fp16-split ------------
__global__ __launch_bounds__(512, 1)
void edge_mma_kernel(const float* __restrict__ ns, const float* __restrict__ ef,
                     const int* __restrict__ fidx, const int* __restrict__ tidx,
                     const float* __restrict__ W1, const float* __restrict__ RW1,
                     const float* __restrict__ b1, const float* __restrict__ b2,
                     const float* __restrict__ Rb1, const float* __restrict__ Rb2,
                     int E)
{
    extern __shared__ float smf[];
    char* smc = reinterpret_cast<char*>(smf);
    const uint32_t smb = smem_u32(smf);
    const int tid = threadIdx.x;
    const int wid = tid >> 5, lane = tid & 31;
    const int wm = wid & 3, wn = wid >> 2;        // 4 m-warps x 4 n-warps
    const int m0 = wm * 16, n0 = wn * 64;
    const int e0 = blockIdx.x * 64;

    float* sBiasF = reinterpret_cast<float*>(smc + SBIAS);
    float* sWefF  = reinterpret_cast<float*>(smc + SWEF);
    float* sEfF   = reinterpret_cast<float*>(smc + SEF);

    // ---- gather X (once, shared by both directions), split to fp16 hi/lo ---
    {
        const int row = tid >> 3, q = tid & 7;    // 64 rows x 8 col-chunks of 16
        int e = e0 + row; if (e >= E) e = E - 1;
        const float4* pf = reinterpret_cast<const float4*>(ns + (size_t)fidx[e] * 128 + q * 16);
        const float4* pt = reinterpret_cast<const float4*>(ns + (size_t)tidx[e] * 128 + q * 16);
        const uint32_t dst = (uint32_t)(row * 136 + q * 16) * 2;
        #pragma unroll
        for (int j = 0; j < 4; ++j) {
            float4 v = pf[j];
            uint32_t lo0, lo1;
            uint32_t hi0 = pack_hi(v.x, v.y, lo0);
            uint32_t hi1 = pack_hi(v.z, v.w, lo1);
            *reinterpret_cast<uint32_t*>(smc + XF_HI + dst + j * 8)     = hi0;
            *reinterpret_cast<uint32_t*>(smc + XF_HI + dst + j * 8 + 4) = hi1;
            *reinterpret_cast<uint32_t*>(smc + XF_LO + dst + j * 8)     = lo0;
            *reinterpret_cast<uint32_t*>(smc + XF_LO + dst + j * 8 + 4) = lo1;
            v = pt[j];
            hi0 = pack_hi(v.x, v.y, lo0);
            hi1 = pack_hi(v.z, v.w, lo1);
            *reinterpret_cast<uint32_t*>(smc + XT_HI + dst + j * 8)     = hi0;
            *reinterpret_cast<uint32_t*>(smc + XT_HI + dst + j * 8 + 4) = hi1;
            *reinterpret_cast<uint32_t*>(smc + XT_LO + dst + j * 8)     = lo0;
            *reinterpret_cast<uint32_t*>(smc + XT_LO + dst + j * 8 + 4) = lo1;
        }
        if (tid < 64) sEfF[tid] = (e0 + tid < E) ? ef[e0 + tid] : 0.f;
    }

    // lane-resolved fragment address components
    const int rA = (lane & 7) + ((lane >> 3) & 1) * 8;   // row within 16
    const int cAo = (lane >> 4) * 8;                     // col offset 0/8
    const uint32_t bB = (uint32_t)(((n0 + (lane & 7)) * 40 + ((lane >> 3) & 1) * 8) * 2);

    float acc[8][4];

    for (int dir = 0; dir < 2; ++dir) {
        const int* iD = dir ? fidx : tidx;
        const float* bias1 = dir ? Rb1 : b1;
        const float* bias2 = dir ? Rb2 : b2;
        const float* wef = (dir ? RW1 : W1) + 65536;   // row k=256 of W1
        const __half* g1h = g_w1[dir][0]; const __half* g1l = g_w1[dir][1];
        const __half* g2h = g_w2[dir][0]; const __half* g2l = g_w2[dir][1];
        const uint32_t fHI = dir ? XT_HI : XF_HI, fLO = dir ? XT_LO : XF_LO;
        const uint32_t sHI = dir ? XF_HI : XT_HI, sLO = dir ? XF_LO : XT_LO;

        __syncthreads();
        if (tid < 256) {
            sBiasF[tid] = bias1[tid];
            sWefF[tid]  = wef[tid];
        }
        __syncthreads();

        // ----------------- layer 1: K=256 MMA + fp32 ef rank-1 --------------
        #pragma unroll
        for (int nf = 0; nf < 8; ++nf) {
            int cc = n0 + nf * 8 + (lane & 3) * 2;
            acc[nf][0] = sBiasF[cc];
            acc[nf][1] = sBiasF[cc + 1];
            acc[nf][2] = acc[nf][0];
            acc[nf][3] = acc[nf][1];
        }
        {
            uint32_t off = (uint32_t)(((m0 + rA) * 136 + cAo) * 2);
            gemm_phase(g1h, g1l, smb, tid,
                       smb + fHI + off, smb + fLO + off,
                       smb + sHI + off, smb + sLO + off, bB, acc);
        }
        // epilogue: ef column (exact fp32), bias already in, ReLU, split -> sH
        {
            const float efr  = sEfF[m0 + (lane >> 2)];
            const float efr8 = sEfF[m0 + 8 + (lane >> 2)];
            const int r0 = m0 + (lane >> 2);
            #pragma unroll
            for (int nf = 0; nf < 8; ++nf) {
                int cc = n0 + nf * 8 + (lane & 3) * 2;
                float w0 = sWefF[cc], w1 = sWefF[cc + 1];
                float x0 = fmaxf(acc[nf][0] + efr * w0, 0.f);
                float x1 = fmaxf(acc[nf][1] + efr * w1, 0.f);
                float x2 = fmaxf(acc[nf][2] + efr8 * w0, 0.f);
                float x3 = fmaxf(acc[nf][3] + efr8 * w1, 0.f);
                uint32_t lo0, lo1;
                uint32_t hi0 = pack_hi(x0, x1, lo0);
                uint32_t hi1 = pack_hi(x2, x3, lo1);
                uint32_t d0 = (uint32_t)((r0 * 264 + cc) * 2);
                uint32_t d1 = (uint32_t)(((r0 + 8) * 264 + cc) * 2);
                *reinterpret_cast<uint32_t*>(smc + SH_HI + d0) = hi0;
                *reinterpret_cast<uint32_t*>(smc + SH_LO + d0) = lo0;
                *reinterpret_cast<uint32_t*>(smc + SH_HI + d1) = hi1;
                *reinterpret_cast<uint32_t*>(smc + SH_LO + d1) = lo1;
            }
        }
        __syncthreads();
        if (tid < 256) sBiasF[tid] = bias2[tid];
        __syncthreads();

        // ----------------- layer 2: K=256 over H -----------------------------
        #pragma unroll
        for (int nf = 0; nf < 8; ++nf) {
            int cc = n0 + nf * 8 + (lane & 3) * 2;
            acc[nf][0] = sBiasF[cc];
            acc[nf][1] = sBiasF[cc + 1];
            acc[nf][2] = acc[nf][0];
            acc[nf][3] = acc[nf][1];
        }
        {
            uint32_t off = (uint32_t)(((m0 + rA) * 264 + cAo) * 2);
            uint32_t h0 = smb + SH_HI + off, l0 = smb + SH_LO + off;
            gemm_phase(g2h, g2l, smb, tid, h0, l0, h0 + 256, l0 + 256, bB, acc);
        }

        // ----------------- scatter: red.v2 into g_agg ------------------------
        {
            const int er = e0 + m0 + (lane >> 2);
            const int er8 = er + 8;
            const int d0 = (er < E) ? iD[er] : 0;
            const int d8 = (er8 < E) ? iD[er8] : 0;
            float* p0 = g_agg + (size_t)d0 * 256;
            float* p8 = g_agg + (size_t)d8 * 256;
            #pragma unroll
            for (int nf = 0; nf < 8; ++nf) {
                int cc = n0 + nf * 8 + (lane & 3) * 2;
                if (er < E)  red2(p0 + cc, acc[nf][0], acc[nf][1]);
                if (er8 < E) red2(p8 + cc, acc[nf][2], acc[nf][3]);
            }
        }
    }
}

// ---------------- node update MLP + residual (FFMA, proven) ----------------
__global__ __launch_bounds__(256, 1)
void node_kernel(const float* __restrict__ node_states,
                 const float* __restrict__ Wn1, const float* __restrict__ bn1,
                 const float* __restrict__ Wn2, const float* __restrict__ bn2,
                 float* __restrict__ out, int N)
{
    extern __shared__ float sm[];
    float* sA = sm;            // 64*256
    float* sS = sm + 16384;    // 64*128
    float* sH = sm + 24576;    // 64*256
    float* sW = sm + 40960;    // 32*256

    const int tid = threadIdx.x;
    const int n0  = blockIdx.x * 64;

    for (int t = tid; t < 64 * 64; t += 256) {
        int n = t >> 6, c = t & 63;
        float4 v = make_float4(0.f, 0.f, 0.f, 0.f);
        if (n0 + n < N)
            v = reinterpret_cast<const float4*>(g_agg)[(size_t)(n0 + n) * 64 + c];
        reinterpret_cast<float4*>(sA)[t] = v;
    }
    for (int t = tid; t < 64 * 32; t += 256) {
        int n = t >> 5, c = t & 31;
        float4 v = make_float4(0.f, 0.f, 0.f, 0.f);
        if (n0 + n < N)
            v = reinterpret_cast<const float4*>(node_states)[(size_t)(n0 + n) * 32 + c];
        reinterpret_cast<float4*>(sS)[t] = v;
    }
    __syncthreads();

    const int wg = tid >> 5, lane = tid & 31;
    const int nBase = wg * 8, j0 = lane * 8;

    float acc[8][8];
    #pragma unroll
    for (int jj = 0; jj < 8; ++jj) {
        float bv = bn1[j0 + jj];
        #pragma unroll
        for (int ii = 0; ii < 8; ++ii) acc[ii][jj] = bv;
    }
    for (int kt = 0; kt < 12; ++kt) {
        __syncthreads();
        {
            const float4* src = reinterpret_cast<const float4*>(Wn1 + kt * 32 * 256);
            float4* dw = reinterpret_cast<float4*>(sW);
            #pragma unroll
            for (int t0 = 0; t0 < 8; ++t0) dw[tid + t0 * 256] = src[tid + t0 * 256];
        }
        __syncthreads();
        const float* Xb; int strd;
        if (kt < 8) { Xb = sA + kt * 32;       strd = 256; }
        else        { Xb = sS + (kt - 8) * 32; strd = 128; }
        #pragma unroll 8
        for (int kk = 0; kk < 32; ++kk) {
            float xv[8];
            #pragma unroll
            for (int ii = 0; ii < 8; ++ii) xv[ii] = Xb[(nBase + ii) * strd + kk];
            float4 w0 = *reinterpret_cast<const float4*>(&sW[kk * 256 + j0]);
            float4 w1 = *reinterpret_cast<const float4*>(&sW[kk * 256 + j0 + 4]);
            float wv[8] = {w0.x, w0.y, w0.z, w0.w, w1.x, w1.y, w1.z, w1.w};
            #pragma unroll
            for (int ii = 0; ii < 8; ++ii)
                #pragma unroll
                for (int jj = 0; jj < 8; ++jj)
                    acc[ii][jj] = fmaf(xv[ii], wv[jj], acc[ii][jj]);
        }
    }
    #pragma unroll
    for (int ii = 0; ii < 8; ++ii) {
        float4 h0 = make_float4(fmaxf(acc[ii][0], 0.f), fmaxf(acc[ii][1], 0.f),
                                fmaxf(acc[ii][2], 0.f), fmaxf(acc[ii][3], 0.f));
        float4 h1 = make_float4(fmaxf(acc[ii][4], 0.f), fmaxf(acc[ii][5], 0.f),
                                fmaxf(acc[ii][6], 0.f), fmaxf(acc[ii][7], 0.f));
        *reinterpret_cast<float4*>(&sH[(nBase + ii) * 256 + j0])     = h0;
        *reinterpret_cast<float4*>(&sH[(nBase + ii) * 256 + j0 + 4]) = h1;
    }

    const int j4 = lane * 4;
    float acc2[8][4];
    #pragma unroll
    for (int jj = 0; jj < 4; ++jj) {
        float bv = bn2[j4 + jj];
        #pragma unroll
        for (int ii = 0; ii < 8; ++ii) acc2[ii][jj] = bv;
    }
    for (int kt = 0; kt < 8; ++kt) {
        __syncthreads();
        {
            const float4* src = reinterpret_cast<const float4*>(Wn2 + kt * 32 * 128);
            float4* dw = reinterpret_cast<float4*>(sW);
            #pragma unroll
            for (int t0 = 0; t0 < 4; ++t0) dw[tid + t0 * 256] = src[tid + t0 * 256];
        }
        __syncthreads();
        #pragma unroll 8
        for (int kk = 0; kk < 32; ++kk) {
            float xv[8];
            #pragma unroll
            for (int ii = 0; ii < 8; ++ii) xv[ii] = sH[(nBase + ii) * 256 + kt * 32 + kk];
            float4 w = *reinterpret_cast<const float4*>(&sW[kk * 128 + j4]);
            float wv[4] = {w.x, w.y, w.z, w.w};
            #pragma unroll
            for (int ii = 0; ii < 8; ++ii)
                #pragma unroll
                for (int jj = 0; jj < 4; ++jj)
                    acc2[ii][jj] = fmaf(xv[ii], wv[jj], acc2[ii][jj]);
        }
    }
    #pragma unroll
    for (int ii = 0; ii < 8; ++ii) {
        int n = n0 + nBase + ii;
        if (n < N) {
            float4 s = *reinterpret_cast<const float4*>(&sS[(nBase + ii) * 128 + j4]);
            float4 o = make_float4(s.x + acc2[ii][0], s.y + acc2[ii][1],
                                   s.z + acc2[ii][2], s.w + acc2[ii][3]);
            *reinterpret_cast<float4*>(&out[(size_t)n * 128 + j4]) = o;
        }
    }
}

// ---------------------------------------------------------------------------
extern "C" void kernel_launch(void* const* d_in, const int* in_sizes, int n_in,
                              void* d_out, int out_size)
{
    const float* node_states = (const float*)d_in[0];
    const float* edge_feat   = (const float*)d_in[1];
    const int*   from_idx    = (const int*)d_in[2];
    const int*   to_idx      = (const int*)d_in[3];
    const float* W1  = (const float*)d_in[4];
    const float* b1  = (const float*)d_in[5];
    const float* W2  = (const float*)d_in[6];
    const float* b2  = (const float*)d_in[7];
    const float* RW1 = (const float*)d_in[8];
    const float* Rb1 = (const float*)d_in[9];
    const float* RW2 = (const float*)d_in[10];
    const float* Rb2 = (const float*)d_in[11];
    const float* Wn1 = (const float*)d_in[12];
    const float* bn1 = (const float*)d_in[13];
    const float* Wn2 = (const float*)d_in[14];
    const float* bn2 = (const float*)d_in[15];
    float* out = (float*)d_out;

    const int N = in_sizes[0] / 128;
    const int E = in_sizes[2];

    __half* w1p; __half* w2p;
    cudaGetSymbolAddress((void**)&w1p, g_w1);
    cudaGetSymbolAddress((void**)&w2p, g_w2);

    cudaFuncSetAttribute(edge_mma_kernel, cudaFuncAttributeMaxDynamicSharedMemorySize, EDGE_SMEM);
    cudaFuncSetAttribute(node_kernel, cudaFuncAttributeMaxDynamicSharedMemorySize, 49152 * 4);

    zero_agg_kernel<<<1024, 256>>>(N * 64);
    prep_w_kernel<<<256, 256>>>(W1,  w1p,              w1p + 65536);
    prep_w_kernel<<<256, 256>>>(RW1, w1p + 2 * 65536,  w1p + 3 * 65536);
    prep_w_kernel<<<256, 256>>>(W2,  w2p,              w2p + 65536);
    prep_w_kernel<<<256, 256>>>(RW2, w2p + 2 * 65536,  w2p + 3 * 65536);
    edge_mma_kernel<<<(E + 63) / 64, 512, EDGE_SMEM>>>(
        node_states, edge_feat, from_idx, to_idx, W1, RW1, b1, b2, Rb1, Rb2, E);
    node_kernel<<<(N + 63) / 64, 256, 49152 * 4>>>(node_states, Wn1, bn1, Wn2, bn2, out, N);
}